// round 1
// baseline (speedup 1.0000x reference)
#include <cuda_runtime.h>

#define NN 100000     // nodes
#define NE 1600000    // edges
#define INF 64        // input features
#define OF 40         // output features
#define NC 10000      // clusters

// ---- scratch (device globals; no dynamic allocation allowed) ----
__device__ float g_u[NN * OF];        // current scaled features  u_k = dinv^a * (...)
__device__ float g_v[NN * OF];        // accumulation target      v = S u
__device__ int   g_deg[NN];
__device__ float g_dinv[NN];
__device__ float g_xc[NC * OF];       // per-cluster feature sums
__device__ int   g_cnt[NC];           // per-cluster node counts

__device__ __forceinline__ void red_add_v4(float* p, float4 v) {
    asm volatile("red.global.add.v4.f32 [%0], {%1,%2,%3,%4};"
                 :: "l"(p), "f"(v.x), "f"(v.y), "f"(v.z), "f"(v.w)
                 : "memory");
}

// deg=1 (self loop), cnt=0, xc=0. Launched with >= NC*OF threads.
__global__ void k_init() {
    int i = blockIdx.x * blockDim.x + threadIdx.x;
    if (i < NN) g_deg[i] = 1;
    if (i < NC) g_cnt[i] = 0;
    if (i < NC * OF) g_xc[i] = 0.f;
}

// in-degree over edge targets + cluster counts. Launched with >= NE threads.
__global__ void k_deg_cnt(const int* __restrict__ row, const int* __restrict__ cl) {
    int i = blockIdx.x * blockDim.x + threadIdx.x;
    if (i < NE) atomicAdd(&g_deg[__ldg(row + i)], 1);
    if (i < NN) atomicAdd(&g_cnt[__ldg(cl + i)], 1);
}

__global__ void k_dinv() {
    int i = blockIdx.x * blockDim.x + threadIdx.x;
    if (i < NN) g_dinv[i] = rsqrtf((float)g_deg[i]);
}

// u0 = dinv * (x @ W^T); v = u0 (self-loop seed for hop 1).
// One thread per node; x row in registers, W in smem.
__global__ void k_transform(const float* __restrict__ x, const float* __restrict__ W) {
    __shared__ float Ws[OF * INF];
    for (int i = threadIdx.x; i < OF * INF; i += blockDim.x) Ws[i] = W[i];
    __syncthreads();
    int n = blockIdx.x * blockDim.x + threadIdx.x;
    if (n >= NN) return;

    float xr[INF];
    const float4* xp = (const float4*)(x + (size_t)n * INF);
#pragma unroll
    for (int i = 0; i < INF / 4; i++) {
        float4 t = __ldg(xp + i);
        xr[4 * i + 0] = t.x; xr[4 * i + 1] = t.y;
        xr[4 * i + 2] = t.z; xr[4 * i + 3] = t.w;
    }
    float d = g_dinv[n];
    float4* up = (float4*)(g_u + (size_t)n * OF);
    float4* vp = (float4*)(g_v + (size_t)n * OF);
#pragma unroll 1
    for (int og = 0; og < OF / 4; og++) {
        float4 acc = make_float4(0.f, 0.f, 0.f, 0.f);
#pragma unroll
        for (int f = 0; f < INF; f += 4) {
            float4 w0 = *(const float4*)&Ws[(og * 4 + 0) * INF + f];
            float4 w1 = *(const float4*)&Ws[(og * 4 + 1) * INF + f];
            float4 w2 = *(const float4*)&Ws[(og * 4 + 2) * INF + f];
            float4 w3 = *(const float4*)&Ws[(og * 4 + 3) * INF + f];
            acc.x += xr[f] * w0.x + xr[f + 1] * w0.y + xr[f + 2] * w0.z + xr[f + 3] * w0.w;
            acc.y += xr[f] * w1.x + xr[f + 1] * w1.y + xr[f + 2] * w1.z + xr[f + 3] * w1.w;
            acc.z += xr[f] * w2.x + xr[f + 1] * w2.y + xr[f + 2] * w2.z + xr[f + 3] * w2.w;
            acc.w += xr[f] * w3.x + xr[f + 1] * w3.y + xr[f + 2] * w3.z + xr[f + 3] * w3.w;
        }
        acc.x *= d; acc.y *= d; acc.z *= d; acc.w *= d;
        up[og] = acc; vp[og] = acc;
    }
}

// v[row] += u[col]  (pure adjacency sum; norm folded into pointwise kernels)
__global__ void k_edges(const int* __restrict__ row, const int* __restrict__ col) {
    int e = blockIdx.x * blockDim.x + threadIdx.x;
    if (e >= NE) return;
    int r = __ldg(row + e);
    int c = __ldg(col + e);
    const float4* src = (const float4*)(g_u + (size_t)c * OF);
    float* dst = g_v + (size_t)r * OF;
    float4 t[OF / 4];
#pragma unroll
    for (int q = 0; q < OF / 4; q++) t[q] = __ldg(src + q);
#pragma unroll
    for (int q = 0; q < OF / 4; q++) red_add_v4(dst + q * 4, t[q]);
}

// u = dinv^2 * v;  v = u  (self-loop seed for next hop)
__global__ void k_rescale() {
    int i = blockIdx.x * blockDim.x + threadIdx.x;
    if (i >= NN * OF / 4) return;
    int n = i / (OF / 4);
    float d = g_dinv[n];
    float d2 = d * d;
    float4 t = ((const float4*)g_v)[i];
    t.x *= d2; t.y *= d2; t.z *= d2; t.w *= d2;
    ((float4*)g_u)[i] = t;
    ((float4*)g_v)[i] = t;
}

// final hop: x3 = dinv * v; accumulate into cluster sums
__global__ void k_final(const int* __restrict__ cl) {
    int i = blockIdx.x * blockDim.x + threadIdx.x;
    if (i >= NN * OF / 4) return;
    int n = i / (OF / 4);
    int q = i % (OF / 4);
    float d = g_dinv[n];
    float4 t = ((const float4*)g_v)[i];
    t.x *= d; t.y *= d; t.z *= d; t.w *= d;
    int c = __ldg(cl + n);
    red_add_v4(g_xc + (size_t)c * OF + q * 4, t);
}

// out[n] = xc[cluster[n]] / max(cnt,1) + b
__global__ void k_out(const int* __restrict__ cl, const float* __restrict__ b,
                      float* __restrict__ out) {
    int i = blockIdx.x * blockDim.x + threadIdx.x;
    if (i >= NN * OF / 4) return;
    int n = i / (OF / 4);
    int q = i % (OF / 4);
    int c = __ldg(cl + n);
    float s = 1.0f / (float)max(g_cnt[c], 1);
    float4 t = ((const float4*)g_xc)[c * (OF / 4) + q];
    float4 bb = ((const float4*)b)[q];
    float4 o;
    o.x = t.x * s + bb.x;
    o.y = t.y * s + bb.y;
    o.z = t.z * s + bb.z;
    o.w = t.w * s + bb.w;
    ((float4*)out)[i] = o;
}

extern "C" void kernel_launch(void* const* d_in, const int* in_sizes, int n_in,
                              void* d_out, int out_size) {
    const float* x = nullptr;
    const int* ei = nullptr;
    const int* cl = nullptr;
    const float* W = nullptr;
    const float* b = nullptr;
    for (int i = 0; i < n_in; i++) {
        switch (in_sizes[i]) {
            case NN * INF: x = (const float*)d_in[i]; break;   // 6,400,000
            case 2 * NE:   ei = (const int*)d_in[i]; break;    // 3,200,000
            case NN:       cl = (const int*)d_in[i]; break;    // 100,000
            case OF * INF: W = (const float*)d_in[i]; break;   // 2,560
            case OF:       b = (const float*)d_in[i]; break;   // 40
            default: break;                                    // num_clusters scalar: ignored
        }
    }
    const int* row = ei;        // targets
    const int* col = ei + NE;   // sources

    const int B = 256;
    k_init<<<(NC * OF + B - 1) / B, B>>>();
    k_deg_cnt<<<(NE + B - 1) / B, B>>>(row, cl);
    k_dinv<<<(NN + B - 1) / B, B>>>();
    k_transform<<<(NN + 127) / 128, 128>>>(x, W);
    for (int h = 0; h < 3; h++) {
        k_edges<<<(NE + B - 1) / B, B>>>(row, col);
        if (h < 2) k_rescale<<<(NN * OF / 4 + B - 1) / B, B>>>();
    }
    k_final<<<(NN * OF / 4 + B - 1) / B, B>>>(cl);
    k_out<<<(NN * OF / 4 + B - 1) / B, B>>>(cl, b, (float*)d_out);
}

// round 4
// speedup vs baseline: 1.5136x; 1.5136x over previous
#include <cuda_runtime.h>

#define NN 100000     // nodes
#define NE 1600000    // edges
#define INF 64        // input features
#define OF 40         // output features
#define NQ (OF / 4)   // 10 float4 quads per row
#define NC 10000      // clusters

// ---- scratch (device globals; no dynamic allocation allowed) ----
__device__ float g_u[NN * OF];
__device__ float g_v[NN * OF];
__device__ int   g_deg[NN];
__device__ float g_dinv[NN];
__device__ float g_xc[NC * OF];
__device__ int   g_cnt[NC];

__device__ __forceinline__ void red_add_v4(float* p, float4 v) {
    asm volatile("red.global.add.v4.f32 [%0], {%1,%2,%3,%4};"
                 :: "l"(p), "f"(v.x), "f"(v.y), "f"(v.z), "f"(v.w)
                 : "memory");
}

__global__ void k_init() {
    int i = blockIdx.x * blockDim.x + threadIdx.x;
    if (i < NN) g_deg[i] = 1;
    if (i < NC) g_cnt[i] = 0;
    if (i < NC * OF) g_xc[i] = 0.f;
}

__global__ void k_deg_cnt(const int* __restrict__ row, const int* __restrict__ cl) {
    int i = blockIdx.x * blockDim.x + threadIdx.x;
    if (i < NE) atomicAdd(&g_deg[__ldg(row + i)], 1);
    if (i < NN) atomicAdd(&g_cnt[__ldg(cl + i)], 1);
}

__global__ void k_dinv() {
    int i = blockIdx.x * blockDim.x + threadIdx.x;
    if (i < NN) g_dinv[i] = rsqrtf((float)g_deg[i]);
}

// u0 = dinv * (x @ W^T); v = u0 (self-loop seed for hop 1).
__global__ void k_transform(const float* __restrict__ x, const float* __restrict__ W) {
    __shared__ float Ws[OF * INF];
    for (int i = threadIdx.x; i < OF * INF; i += blockDim.x) Ws[i] = W[i];
    __syncthreads();
    int n = blockIdx.x * blockDim.x + threadIdx.x;
    if (n >= NN) return;

    float xr[INF];
    const float4* xp = (const float4*)(x + (size_t)n * INF);
#pragma unroll
    for (int i = 0; i < INF / 4; i++) {
        float4 t = __ldg(xp + i);
        xr[4 * i + 0] = t.x; xr[4 * i + 1] = t.y;
        xr[4 * i + 2] = t.z; xr[4 * i + 3] = t.w;
    }
    float d = g_dinv[n];
    float4* up = (float4*)(g_u + (size_t)n * OF);
    float4* vp = (float4*)(g_v + (size_t)n * OF);
#pragma unroll 1
    for (int og = 0; og < NQ; og++) {
        float4 acc = make_float4(0.f, 0.f, 0.f, 0.f);
#pragma unroll
        for (int f = 0; f < INF; f += 4) {
            float4 w0 = *(const float4*)&Ws[(og * 4 + 0) * INF + f];
            float4 w1 = *(const float4*)&Ws[(og * 4 + 1) * INF + f];
            float4 w2 = *(const float4*)&Ws[(og * 4 + 2) * INF + f];
            float4 w3 = *(const float4*)&Ws[(og * 4 + 3) * INF + f];
            acc.x += xr[f] * w0.x + xr[f + 1] * w0.y + xr[f + 2] * w0.z + xr[f + 3] * w0.w;
            acc.y += xr[f] * w1.x + xr[f + 1] * w1.y + xr[f + 2] * w1.z + xr[f + 3] * w1.w;
            acc.z += xr[f] * w2.x + xr[f + 1] * w2.y + xr[f + 2] * w2.z + xr[f + 3] * w2.w;
            acc.w += xr[f] * w3.x + xr[f + 1] * w3.y + xr[f + 2] * w3.z + xr[f + 3] * w3.w;
        }
        acc.x *= d; acc.y *= d; acc.z *= d; acc.w *= d;
        up[og] = acc; vp[og] = acc;
    }
}

// v[row] += u[col] — one thread per (edge, quad): 10 consecutive lanes cover
// one 160B row contiguously -> ~4 distinct rows per warp per LDG/RED instr
// instead of 32, collapsing the L1tex wavefront count.
__global__ void __launch_bounds__(256) k_edges(const int* __restrict__ row,
                                               const int* __restrict__ col) {
    int i = blockIdx.x * blockDim.x + threadIdx.x;
    if (i >= NE * NQ) return;
    int e = i / NQ;
    int q = i - e * NQ;
    int r = __ldg(row + e);
    int c = __ldg(col + e);
    float4 t = __ldg((const float4*)(g_u + (size_t)c * OF) + q);
    red_add_v4(g_v + (size_t)r * OF + q * 4, t);
}

// u = dinv^2 * v;  v = u
__global__ void k_rescale() {
    int i = blockIdx.x * blockDim.x + threadIdx.x;
    if (i >= NN * NQ) return;
    int n = i / NQ;
    float d = g_dinv[n];
    float d2 = d * d;
    float4 t = ((const float4*)g_v)[i];
    t.x *= d2; t.y *= d2; t.z *= d2; t.w *= d2;
    ((float4*)g_u)[i] = t;
    ((float4*)g_v)[i] = t;
}

// final hop: x3 = dinv * v; accumulate into cluster sums
__global__ void k_final(const int* __restrict__ cl) {
    int i = blockIdx.x * blockDim.x + threadIdx.x;
    if (i >= NN * NQ) return;
    int n = i / NQ;
    int q = i - n * NQ;
    float d = g_dinv[n];
    float4 t = ((const float4*)g_v)[i];
    t.x *= d; t.y *= d; t.z *= d; t.w *= d;
    int c = __ldg(cl + n);
    red_add_v4(g_xc + (size_t)c * OF + q * 4, t);
}

// out[n] = xc[cluster[n]] / max(cnt,1) + b
__global__ void k_out(const int* __restrict__ cl, const float* __restrict__ b,
                      float* __restrict__ out) {
    int i = blockIdx.x * blockDim.x + threadIdx.x;
    if (i >= NN * NQ) return;
    int n = i / NQ;
    int q = i - n * NQ;
    int c = __ldg(cl + n);
    float s = 1.0f / (float)max(g_cnt[c], 1);
    float4 t = ((const float4*)g_xc)[c * NQ + q];
    float4 bb = ((const float4*)b)[q];
    float4 o;
    o.x = t.x * s + bb.x;
    o.y = t.y * s + bb.y;
    o.z = t.z * s + bb.z;
    o.w = t.w * s + bb.w;
    ((float4*)out)[i] = o;
}

extern "C" void kernel_launch(void* const* d_in, const int* in_sizes, int n_in,
                              void* d_out, int out_size) {
    const float* x = nullptr;
    const int* ei = nullptr;
    const int* cl = nullptr;
    const float* W = nullptr;
    const float* b = nullptr;
    for (int i = 0; i < n_in; i++) {
        switch (in_sizes[i]) {
            case NN * INF: x = (const float*)d_in[i]; break;
            case 2 * NE:   ei = (const int*)d_in[i]; break;
            case NN:       cl = (const int*)d_in[i]; break;
            case OF * INF: W = (const float*)d_in[i]; break;
            case OF:       b = (const float*)d_in[i]; break;
            default: break;
        }
    }
    const int* row = ei;        // targets
    const int* col = ei + NE;   // sources

    const int B = 256;
    k_init<<<(NC * OF + B - 1) / B, B>>>();
    k_deg_cnt<<<(NE + B - 1) / B, B>>>(row, cl);
    k_dinv<<<(NN + B - 1) / B, B>>>();
    k_transform<<<(NN + 127) / 128, 128>>>(x, W);
    for (int h = 0; h < 3; h++) {
        k_edges<<<(NE * NQ + B - 1) / B, B>>>(row, col);
        if (h < 2) k_rescale<<<(NN * NQ + B - 1) / B, B>>>();
    }
    k_final<<<(NN * NQ + B - 1) / B, B>>>(cl);
    k_out<<<(NN * NQ + B - 1) / B, B>>>(cl, b, (float*)d_out);
}

// round 5
// speedup vs baseline: 2.4857x; 1.6422x over previous
#include <cuda_runtime.h>

#define NN 100000     // nodes
#define NE 1600000    // edges
#define INF 64        // input features
#define OF 40         // output features
#define NQ (OF / 4)   // 10 float4 quads per row
#define NC 10000      // clusters
#define SCAN_BS 1024
#define SCAN_NB ((NN + SCAN_BS - 1) / SCAN_BS)

// ---- scratch (device globals; no dynamic allocation allowed) ----
__device__ float g_u[NN * OF];
__device__ float g_v[NN * OF];
__device__ int   g_deg[NN];     // in-edge histogram (no self loop)
__device__ float g_dinv[NN];    // rsqrt(deg+1)
__device__ int   g_off[NN];     // CSR row offsets (exclusive scan of deg)
__device__ int   g_cur[NN];     // scatter cursors
__device__ int   g_csr[NE];     // CSR column (source) indices
__device__ int   g_part[SCAN_NB + 1];
__device__ float g_xc[NC * OF];
__device__ int   g_cnt[NC];

__device__ __forceinline__ void red_add_v4(float* p, float4 v) {
    asm volatile("red.global.add.v4.f32 [%0], {%1,%2,%3,%4};"
                 :: "l"(p), "f"(v.x), "f"(v.y), "f"(v.z), "f"(v.w)
                 : "memory");
}

__global__ void k_init() {
    int i = blockIdx.x * blockDim.x + threadIdx.x;
    if (i < NN) g_deg[i] = 0;
    if (i < NC) g_cnt[i] = 0;
    if (i < NC * OF) g_xc[i] = 0.f;
}

__global__ void k_hist(const int* __restrict__ row, const int* __restrict__ cl) {
    int i = blockIdx.x * blockDim.x + threadIdx.x;
    if (i < NE) atomicAdd(&g_deg[__ldg(row + i)], 1);
    if (i < NN) atomicAdd(&g_cnt[__ldg(cl + i)], 1);
}

// ---- exclusive scan of g_deg -> g_off ----
__global__ void k_scan1() {
    __shared__ int sh[SCAN_BS];
    int i = blockIdx.x * SCAN_BS + threadIdx.x;
    int v = (i < NN) ? g_deg[i] : 0;
    sh[threadIdx.x] = v;
    __syncthreads();
#pragma unroll
    for (int off = 1; off < SCAN_BS; off <<= 1) {
        int t = (threadIdx.x >= off) ? sh[threadIdx.x - off] : 0;
        __syncthreads();
        sh[threadIdx.x] += t;
        __syncthreads();
    }
    if (i < NN) g_off[i] = sh[threadIdx.x] - v;
    if (threadIdx.x == SCAN_BS - 1) g_part[blockIdx.x] = sh[SCAN_BS - 1];
}
__global__ void k_scan2() {
    if (threadIdx.x == 0) {
        int run = 0;
        for (int i = 0; i < SCAN_NB; i++) { int t = g_part[i]; g_part[i] = run; run += t; }
    }
}
__global__ void k_scan3() {
    int i = blockIdx.x * blockDim.x + threadIdx.x;
    if (i < NN) {
        int o = g_off[i] + g_part[i >> 10];
        g_off[i] = o;
        g_cur[i] = o;
        g_dinv[i] = rsqrtf((float)(g_deg[i] + 1));
    }
}

__global__ void k_scatter(const int* __restrict__ row, const int* __restrict__ col) {
    int i = blockIdx.x * blockDim.x + threadIdx.x;
    if (i >= NE) return;
    int r = __ldg(row + i);
    int pos = atomicAdd(&g_cur[r], 1);
    g_csr[pos] = __ldg(col + i);
}

// u0 = dinv * (x @ W^T), packed fma.rn.f32x2 (2 outputs per FMA).
__global__ void __launch_bounds__(128) k_transform(const float* __restrict__ x,
                                                   const float* __restrict__ W) {
    __shared__ float Wp[INF * OF];   // f-major: Wp[f*OF + o]
    for (int i = threadIdx.x; i < INF * OF; i += blockDim.x) {
        int f = i / OF, o = i - f * OF;
        Wp[i] = W[o * INF + f];
    }
    __syncthreads();
    int n = blockIdx.x * blockDim.x + threadIdx.x;
    if (n >= NN) return;

    unsigned long long acc[OF / 2];
#pragma unroll
    for (int p = 0; p < OF / 2; p++) acc[p] = 0ull;

    const float4* xp = (const float4*)(x + (size_t)n * INF);
#pragma unroll 1
    for (int fc = 0; fc < INF; fc += 8) {
        float4 a = __ldg(xp + fc / 4);
        float4 b2 = __ldg(xp + fc / 4 + 1);
        float xs[8] = {a.x, a.y, a.z, a.w, b2.x, b2.y, b2.z, b2.w};
#pragma unroll
        for (int ff = 0; ff < 8; ff++) {
            int f = fc + ff;
            unsigned long long xx;
            asm("mov.b64 %0, {%1, %1};" : "=l"(xx) : "f"(xs[ff]));
            const ulonglong2* wrow = (const ulonglong2*)(Wp + f * OF);
#pragma unroll
            for (int p = 0; p < NQ; p++) {
                ulonglong2 w = wrow[p];
                asm("fma.rn.f32x2 %0, %1, %2, %0;" : "+l"(acc[2 * p]) : "l"(w.x), "l"(xx));
                asm("fma.rn.f32x2 %0, %1, %2, %0;" : "+l"(acc[2 * p + 1]) : "l"(w.y), "l"(xx));
            }
        }
    }
    float dv = g_dinv[n];
    unsigned long long dd;
    asm("mov.b64 %0, {%1, %1};" : "=l"(dd) : "f"(dv));
    ulonglong2* up = (ulonglong2*)(g_u + (size_t)n * OF);
#pragma unroll
    for (int p = 0; p < NQ; p++) {
        unsigned long long r0, r1;
        asm("mul.rn.f32x2 %0, %1, %2;" : "=l"(r0) : "l"(acc[2 * p]), "l"(dd));
        asm("mul.rn.f32x2 %0, %1, %2;" : "=l"(r1) : "l"(acc[2 * p + 1]), "l"(dd));
        ulonglong2 st; st.x = r0; st.y = r1;
        up[p] = st;
    }
}

// Gather hop. DIR=0: g_u -> g_v.  DIR=1: g_v -> g_u.  LAST: g_u -> cluster RED.
// 10 lanes per node (one float4 quad each), 32 nodes per 320-thread block.
template <int DIR, int LAST>
__global__ void __launch_bounds__(320) k_hop(const int* __restrict__ cl) {
    int tid = threadIdx.x;
    int g = tid / NQ;
    int q = tid - g * NQ;
    int n = blockIdx.x * 32 + g;
    if (n >= NN) return;

    const float4* base = (const float4*)(DIR ? g_v : g_u);
    int s = g_off[n];
    int e = s + g_deg[n];
    float4 acc = __ldg(base + (size_t)n * NQ + q);  // self loop

    int j = s;
    for (; j + 4 <= e; j += 4) {
        int c0 = __ldg(g_csr + j);
        int c1 = __ldg(g_csr + j + 1);
        int c2 = __ldg(g_csr + j + 2);
        int c3 = __ldg(g_csr + j + 3);
        float4 a = __ldg(base + (size_t)c0 * NQ + q);
        float4 b2 = __ldg(base + (size_t)c1 * NQ + q);
        float4 c = __ldg(base + (size_t)c2 * NQ + q);
        float4 d = __ldg(base + (size_t)c3 * NQ + q);
        acc.x += a.x + b2.x + c.x + d.x;
        acc.y += a.y + b2.y + c.y + d.y;
        acc.z += a.z + b2.z + c.z + d.z;
        acc.w += a.w + b2.w + c.w + d.w;
    }
    for (; j < e; j++) {
        int c0 = __ldg(g_csr + j);
        float4 a = __ldg(base + (size_t)c0 * NQ + q);
        acc.x += a.x; acc.y += a.y; acc.z += a.z; acc.w += a.w;
    }

    float d = g_dinv[n];
    float sc = LAST ? d : d * d;
    acc.x *= sc; acc.y *= sc; acc.z *= sc; acc.w *= sc;
    if (LAST) {
        int c = __ldg(cl + n);
        red_add_v4(g_xc + (size_t)c * OF + q * 4, acc);
    } else {
        float4* outp = (float4*)(DIR ? g_u : g_v);
        outp[(size_t)n * NQ + q] = acc;
    }
}

// out[n] = xc[cluster[n]] / max(cnt,1) + b
__global__ void k_out(const int* __restrict__ cl, const float* __restrict__ b,
                      float* __restrict__ out) {
    int i = blockIdx.x * blockDim.x + threadIdx.x;
    if (i >= NN * NQ) return;
    int n = i / NQ;
    int q = i - n * NQ;
    int c = __ldg(cl + n);
    float s = 1.0f / (float)max(g_cnt[c], 1);
    float4 t = ((const float4*)g_xc)[c * NQ + q];
    float4 bb = ((const float4*)b)[q];
    float4 o;
    o.x = t.x * s + bb.x;
    o.y = t.y * s + bb.y;
    o.z = t.z * s + bb.z;
    o.w = t.w * s + bb.w;
    ((float4*)out)[i] = o;
}

extern "C" void kernel_launch(void* const* d_in, const int* in_sizes, int n_in,
                              void* d_out, int out_size) {
    const float* x = nullptr;
    const int* ei = nullptr;
    const int* cl = nullptr;
    const float* W = nullptr;
    const float* b = nullptr;
    for (int i = 0; i < n_in; i++) {
        switch (in_sizes[i]) {
            case NN * INF: x = (const float*)d_in[i]; break;
            case 2 * NE:   ei = (const int*)d_in[i]; break;
            case NN:       cl = (const int*)d_in[i]; break;
            case OF * INF: W = (const float*)d_in[i]; break;
            case OF:       b = (const float*)d_in[i]; break;
            default: break;
        }
    }
    const int* row = ei;        // targets
    const int* col = ei + NE;   // sources

    const int B = 256;
    k_init<<<(NC * OF + B - 1) / B, B>>>();
    k_hist<<<(NE + B - 1) / B, B>>>(row, cl);
    k_scan1<<<SCAN_NB, SCAN_BS>>>();
    k_scan2<<<1, 32>>>();
    k_scan3<<<(NN + B - 1) / B, B>>>();
    k_scatter<<<(NE + B - 1) / B, B>>>(row, col);
    k_transform<<<(NN + 127) / 128, 128>>>(x, W);

    const int HG = (NN + 31) / 32;
    k_hop<0, 0><<<HG, 320>>>(cl);   // u -> v
    k_hop<1, 0><<<HG, 320>>>(cl);   // v -> u
    k_hop<0, 1><<<HG, 320>>>(cl);   // u -> cluster sums
    k_out<<<(NN * NQ + B - 1) / B, B>>>(cl, b, (float*)d_out);
}

// round 8
// speedup vs baseline: 2.8354x; 1.1407x over previous
#include <cuda_runtime.h>

#define NN 100000     // nodes
#define NE 1600000    // edges
#define INF 64        // input features
#define OF 40         // output features
#define NQ (OF / 4)   // 10 float4 quads per row
#define NC 10000      // clusters
#define SNB ((NN + 1023) / 1024)   // 98 scan blocks (tile = 256 thr * 4 items)

// ---- scratch (device globals; no dynamic allocation allowed) ----
__device__ __align__(16) float g_u[NN * OF];
__device__ __align__(16) float g_v[NN * OF];
__device__ __align__(16) int   g_deg[NN];     // in-edge histogram (no self loop)
__device__ __align__(16) float g_dinv[NN];    // rsqrt(deg+1)
__device__ __align__(16) int   g_off[NN];     // CSR row offsets (exclusive scan of deg)
__device__ __align__(16) int   g_cur[NN];     // scatter cursors
__device__ __align__(16) int   g_csr[NE];     // CSR column (source) indices
__device__ __align__(16) int   g_part[SNB];   // per-block totals
__device__ __align__(16) float g_xc[NC * OF];
__device__ __align__(16) int   g_cnt[NC];

__device__ __forceinline__ void red_add_v4(float* p, float4 v) {
    asm volatile("red.global.add.v4.f32 [%0], {%1,%2,%3,%4};"
                 :: "l"(p), "f"(v.x), "f"(v.y), "f"(v.z), "f"(v.w)
                 : "memory");
}

// zero deg/cnt/xc (kernel, not memset: must be IN the captured graph)
__global__ void k_init() {
    int i = blockIdx.x * blockDim.x + threadIdx.x;
    if (i < NN) g_deg[i] = 0;
    if (i < NC) g_cnt[i] = 0;
    if (i < NC * OF) g_xc[i] = 0.f;
}

__global__ void k_hist(const int* __restrict__ row, const int* __restrict__ cl) {
    int i = blockIdx.x * blockDim.x + threadIdx.x;
    if (i < NE) atomicAdd(&g_deg[__ldg(row + i)], 1);
    if (i < NN) atomicAdd(&g_cnt[__ldg(cl + i)], 1);
}

__global__ void k_dinv() {
    int i = blockIdx.x * blockDim.x + threadIdx.x;
    if (i < NN) g_dinv[i] = rsqrtf((float)(g_deg[i] + 1));
}

// Pass A: per-block exclusive offsets (no cross-block base) + block totals.
__global__ void __launch_bounds__(256) k_scanA() {
    __shared__ int warp_sums[8];
    int lane = threadIdx.x & 31, wid = threadIdx.x >> 5;
    int idx = blockIdx.x * 1024 + threadIdx.x * 4;

    int4 d = make_int4(0, 0, 0, 0);
    if (idx + 3 < NN) d = *(const int4*)(g_deg + idx);
    else {
        if (idx < NN)     d.x = g_deg[idx];
        if (idx + 1 < NN) d.y = g_deg[idx + 1];
        if (idx + 2 < NN) d.z = g_deg[idx + 2];
    }
    int s3 = d.x + d.y + d.z + d.w;

    int v = s3;
#pragma unroll
    for (int o = 1; o < 32; o <<= 1) {
        int t = __shfl_up_sync(~0u, v, o);
        if (lane >= o) v += t;
    }
    if (lane == 31) warp_sums[wid] = v;
    __syncthreads();
    if (wid == 0) {
        int w = (lane < 8) ? warp_sums[lane] : 0;
#pragma unroll
        for (int o = 1; o < 8; o <<= 1) {
            int t = __shfl_up_sync(~0u, w, o);
            if (lane >= o) w += t;
        }
        if (lane < 8) warp_sums[lane] = w;
    }
    __syncthreads();
    int excl = (v - s3) + (wid ? warp_sums[wid - 1] : 0);

    int e0 = excl, e1 = e0 + d.x, e2 = e1 + d.y, e3 = e2 + d.z;
    if (idx + 3 < NN) {
        *(int4*)(g_off + idx) = make_int4(e0, e1, e2, e3);
    } else {
        int ee[4] = {e0, e1, e2, e3};
        for (int t = 0; t < 4; t++)
            if (idx + t < NN) g_off[idx + t] = ee[t];
    }
    if (threadIdx.x == 0) g_part[blockIdx.x] = warp_sums[7];
}

// Pass B: each block redundantly computes its base from the 98 partials,
// then finalizes g_off and g_cur.
__global__ void __launch_bounds__(256) k_scanB() {
    __shared__ int sh_part[SNB];
    __shared__ int sh_base;
    for (int t = threadIdx.x; t < SNB; t += blockDim.x) sh_part[t] = g_part[t];
    __syncthreads();
    if (threadIdx.x == 0) {
        int base = 0;
        for (int j = 0; j < (int)blockIdx.x; j++) base += sh_part[j];
        sh_base = base;
    }
    __syncthreads();
    int base = sh_base;
    int idx = blockIdx.x * 1024 + threadIdx.x * 4;
    if (idx + 3 < NN) {
        int4 o = *(const int4*)(g_off + idx);
        o.x += base; o.y += base; o.z += base; o.w += base;
        *(int4*)(g_off + idx) = o;
        *(int4*)(g_cur + idx) = o;
    } else {
        for (int t = 0; t < 4; t++)
            if (idx + t < NN) {
                int o = g_off[idx + t] + base;
                g_off[idx + t] = o;
                g_cur[idx + t] = o;
            }
    }
}

__global__ void k_scatter(const int* __restrict__ row, const int* __restrict__ col) {
    int i = blockIdx.x * blockDim.x + threadIdx.x;
    if (i >= NE) return;
    int r = __ldg(row + i);
    int pos = atomicAdd(&g_cur[r], 1);
    g_csr[pos] = __ldg(col + i);
}

// u0 = dinv * (x @ W^T), packed fma.rn.f32x2 (2 outputs per FMA).
__global__ void __launch_bounds__(128) k_transform(const float* __restrict__ x,
                                                   const float* __restrict__ W) {
    __shared__ float Wp[INF * OF];   // f-major: Wp[f*OF + o]
    for (int i = threadIdx.x; i < INF * OF; i += blockDim.x) {
        int f = i / OF, o = i - f * OF;
        Wp[i] = W[o * INF + f];
    }
    __syncthreads();
    int n = blockIdx.x * blockDim.x + threadIdx.x;
    if (n >= NN) return;

    unsigned long long acc[OF / 2];
#pragma unroll
    for (int p = 0; p < OF / 2; p++) acc[p] = 0ull;

    const float4* xp = (const float4*)(x + (size_t)n * INF);
#pragma unroll 1
    for (int fc = 0; fc < INF; fc += 8) {
        float4 a = __ldg(xp + fc / 4);
        float4 b2 = __ldg(xp + fc / 4 + 1);
        float xs[8] = {a.x, a.y, a.z, a.w, b2.x, b2.y, b2.z, b2.w};
#pragma unroll
        for (int ff = 0; ff < 8; ff++) {
            int f = fc + ff;
            unsigned long long xx;
            asm("mov.b64 %0, {%1, %1};" : "=l"(xx) : "f"(xs[ff]));
            const ulonglong2* wrow = (const ulonglong2*)(Wp + f * OF);
#pragma unroll
            for (int p = 0; p < NQ; p++) {
                ulonglong2 w = wrow[p];
                asm("fma.rn.f32x2 %0, %1, %2, %0;" : "+l"(acc[2 * p]) : "l"(w.x), "l"(xx));
                asm("fma.rn.f32x2 %0, %1, %2, %0;" : "+l"(acc[2 * p + 1]) : "l"(w.y), "l"(xx));
            }
        }
    }
    float dv = g_dinv[n];
    unsigned long long dd;
    asm("mov.b64 %0, {%1, %1};" : "=l"(dd) : "f"(dv));
    ulonglong2* up = (ulonglong2*)(g_u + (size_t)n * OF);
#pragma unroll
    for (int p = 0; p < NQ; p++) {
        unsigned long long r0, r1;
        asm("mul.rn.f32x2 %0, %1, %2;" : "=l"(r0) : "l"(acc[2 * p]), "l"(dd));
        asm("mul.rn.f32x2 %0, %1, %2;" : "=l"(r1) : "l"(acc[2 * p + 1]), "l"(dd));
        ulonglong2 st; st.x = r0; st.y = r1;
        up[p] = st;
    }
}

// Gather hop. DIR=0: g_u -> g_v.  DIR=1: g_v -> g_u.  LAST: g_u -> cluster RED.
// 10 lanes per node (one float4 quad each), 32 nodes per 320-thread block.
template <int DIR, int LAST>
__global__ void __launch_bounds__(320) k_hop(const int* __restrict__ cl) {
    int tid = threadIdx.x;
    int g = tid / NQ;
    int q = tid - g * NQ;
    int n = blockIdx.x * 32 + g;
    if (n >= NN) return;

    const float4* base = (const float4*)(DIR ? g_v : g_u);
    int s = g_off[n];
    int e = s + g_deg[n];
    float4 acc = __ldg(base + (size_t)n * NQ + q);  // self loop

    int j = s;
    for (; j + 4 <= e; j += 4) {
        int c0 = __ldg(g_csr + j);
        int c1 = __ldg(g_csr + j + 1);
        int c2 = __ldg(g_csr + j + 2);
        int c3 = __ldg(g_csr + j + 3);
        float4 a = __ldg(base + (size_t)c0 * NQ + q);
        float4 b2 = __ldg(base + (size_t)c1 * NQ + q);
        float4 c = __ldg(base + (size_t)c2 * NQ + q);
        float4 d = __ldg(base + (size_t)c3 * NQ + q);
        acc.x += a.x + b2.x + c.x + d.x;
        acc.y += a.y + b2.y + c.y + d.y;
        acc.z += a.z + b2.z + c.z + d.z;
        acc.w += a.w + b2.w + c.w + d.w;
    }
    for (; j < e; j++) {
        int c0 = __ldg(g_csr + j);
        float4 a = __ldg(base + (size_t)c0 * NQ + q);
        acc.x += a.x; acc.y += a.y; acc.z += a.z; acc.w += a.w;
    }

    float dv = g_dinv[n];
    float sc = LAST ? dv : dv * dv;
    acc.x *= sc; acc.y *= sc; acc.z *= sc; acc.w *= sc;
    if (LAST) {
        int c = __ldg(cl + n);
        red_add_v4(g_xc + (size_t)c * OF + q * 4, acc);
    } else {
        float4* outp = (float4*)(DIR ? g_u : g_v);
        outp[(size_t)n * NQ + q] = acc;
    }
}

// out[n] = xc[cluster[n]] / max(cnt,1) + b
__global__ void k_out(const int* __restrict__ cl, const float* __restrict__ b,
                      float* __restrict__ out) {
    int i = blockIdx.x * blockDim.x + threadIdx.x;
    if (i >= NN * NQ) return;
    int n = i / NQ;
    int q = i - n * NQ;
    int c = __ldg(cl + n);
    float s = 1.0f / (float)max(g_cnt[c], 1);
    float4 t = ((const float4*)g_xc)[c * NQ + q];
    float4 bb = ((const float4*)b)[q];
    float4 o;
    o.x = t.x * s + bb.x;
    o.y = t.y * s + bb.y;
    o.z = t.z * s + bb.z;
    o.w = t.w * s + bb.w;
    ((float4*)out)[i] = o;
}

// side stream + events: created ONCE on the first (correctness, non-captured)
// call via magic static; work per call is identical, so determinism holds.
struct Aux {
    cudaStream_t s2;
    cudaEvent_t ev0, ev2;
    bool ok;
    Aux() {
        ok = (cudaStreamCreateWithFlags(&s2, cudaStreamNonBlocking) == cudaSuccess) &&
             (cudaEventCreateWithFlags(&ev0, cudaEventDisableTiming) == cudaSuccess) &&
             (cudaEventCreateWithFlags(&ev2, cudaEventDisableTiming) == cudaSuccess);
    }
};

extern "C" void kernel_launch(void* const* d_in, const int* in_sizes, int n_in,
                              void* d_out, int out_size) {
    const float* x = nullptr;
    const int* ei = nullptr;
    const int* cl = nullptr;
    const float* W = nullptr;
    const float* b = nullptr;
    for (int i = 0; i < n_in; i++) {
        switch (in_sizes[i]) {
            case NN * INF: x = (const float*)d_in[i]; break;
            case 2 * NE:   ei = (const int*)d_in[i]; break;
            case NN:       cl = (const int*)d_in[i]; break;
            case OF * INF: W = (const float*)d_in[i]; break;
            case OF:       b = (const float*)d_in[i]; break;
            default: break;
        }
    }
    const int* row = ei;        // targets
    const int* col = ei + NE;   // sources

    static Aux aux;             // first call is the (uncaptured) correctness run

    const int B = 256;
    k_init<<<(NC * OF + B - 1) / B, B>>>();
    k_hist<<<(NE + B - 1) / B, B>>>(row, cl);

    if (aux.ok) {
        // fork: dinv + transform on s2, CSR build on legacy — independent paths
        cudaEventRecord(aux.ev0, 0);
        cudaStreamWaitEvent(aux.s2, aux.ev0, 0);
        k_dinv<<<(NN + B - 1) / B, B, 0, aux.s2>>>();
        k_transform<<<(NN + 127) / 128, 128, 0, aux.s2>>>(x, W);
        cudaEventRecord(aux.ev2, aux.s2);

        k_scanA<<<SNB, 256>>>();
        k_scanB<<<SNB, 256>>>();
        k_scatter<<<(NE + B - 1) / B, B>>>(row, col);
        cudaStreamWaitEvent(0, aux.ev2, 0);   // join before hops
    } else {
        k_dinv<<<(NN + B - 1) / B, B>>>();
        k_scanA<<<SNB, 256>>>();
        k_scanB<<<SNB, 256>>>();
        k_scatter<<<(NE + B - 1) / B, B>>>(row, col);
        k_transform<<<(NN + 127) / 128, 128>>>(x, W);
    }

    const int HG = (NN + 31) / 32;
    k_hop<0, 0><<<HG, 320>>>(cl);   // u -> v
    k_hop<1, 0><<<HG, 320>>>(cl);   // v -> u
    k_hop<0, 1><<<HG, 320>>>(cl);   // u -> cluster sums
    k_out<<<(NN * NQ + B - 1) / B, B>>>(cl, b, (float*)d_out);
}